// round 12
// baseline (speedup 1.0000x reference)
#include <cuda_runtime.h>

#define NN 100000
#define NE 600000
#define NG 512
#define FD 128
#define SCAN_B 1024
#define NB_SCAN ((NN + SCAN_B - 1) / SCAN_B)   // 98

// Scratch (allocation-free rule: __device__ globals). No float atomics anywhere.
__device__ float g_hw [NN * FD];   // h @ W
__device__ float g_agg[NN * FD];   // aggregated layer output
__device__ float g_dis[NN];        // deg^{-1/2}
__device__ int   g_deg[NN];        // in-degree (excluding self loop)
__device__ int   g_scan[NN];       // inclusive per-block scan
__device__ int   g_bsum[NB_SCAN];
__device__ int   g_boff[NB_SCAN];
__device__ int   g_rowstart[NN];   // CSR row starts (exclusive scan)
__device__ int   g_cursor[NN];     // fill cursors
__device__ int   g_csrc[NE];       // CSR: src lists grouped by dst
__device__ int   g_gstart[NG + 1]; // graph segment starts (batch is sorted)

// ---------------------------------------------------------------------------
__global__ void k_zero() {
    int i = blockIdx.x * blockDim.x + threadIdx.x;
    if (i < NN) g_deg[i] = 0;
}

__global__ void k_count(const int* __restrict__ ei) {
    int e = blockIdx.x * blockDim.x + threadIdx.x;
    if (e < NE) atomicAdd(&g_deg[ei[NE + e]], 1);
}

__global__ void __launch_bounds__(SCAN_B) k_scan1() {
    __shared__ int s[SCAN_B];
    int tid = threadIdx.x;
    int i = blockIdx.x * SCAN_B + tid;
    s[tid] = (i < NN) ? g_deg[i] : 0;
    __syncthreads();
#pragma unroll
    for (int off = 1; off < SCAN_B; off <<= 1) {
        int v = (tid >= off) ? s[tid - off] : 0;
        __syncthreads();
        s[tid] += v;
        __syncthreads();
    }
    if (i < NN) g_scan[i] = s[tid];
    if (tid == SCAN_B - 1) g_bsum[blockIdx.x] = s[tid];
}

__global__ void __launch_bounds__(128) k_scan2() {
    __shared__ int s[128];
    int t = threadIdx.x;
    int v = (t < NB_SCAN) ? g_bsum[t] : 0;
    s[t] = v;
    __syncthreads();
#pragma unroll
    for (int off = 1; off < 128; off <<= 1) {
        int u = (t >= off) ? s[t - off] : 0;
        __syncthreads();
        s[t] += u;
        __syncthreads();
    }
    if (t < NB_SCAN) g_boff[t] = s[t] - v;   // exclusive
}

__global__ void k_scan3() {
    int i = blockIdx.x * blockDim.x + threadIdx.x;
    if (i < NN) {
        int excl = g_scan[i] + g_boff[i >> 10] - g_deg[i];
        g_rowstart[i] = excl;
        g_cursor[i]   = excl;
        g_dis[i] = rsqrtf(1.0f + (float)g_deg[i]);
    }
}

__global__ void k_fill(const int* __restrict__ ei) {
    int e = blockIdx.x * blockDim.x + threadIdx.x;
    if (e < NE) {
        int s = ei[e];
        int d = ei[NE + e];
        int pos = atomicAdd(&g_cursor[d], 1);
        g_csrc[pos] = s;
    }
}

__global__ void k_gstart(const int* __restrict__ batch) {
    int i = blockIdx.x * blockDim.x + threadIdx.x;
    if (i <= NN) {
        int prev = (i == 0) ? -1 : batch[i - 1];
        int cur  = (i < NN) ? batch[i] : NG;
        for (int g = prev + 1; g <= cur; g++) g_gstart[g] = i;
    }
}

// ---------------------------------------------------------------------------
// Tensor-core GEMM: Out[NN,128] = f(A)[NN,128] @ W[128,128]
// Split-TF32 (3 mma: hi*hi + hi*lo + lo*hi) -> fp32-grade accuracy.
// Block: 128 rows x 128 cols, 256 threads (8 warps). Warp = 32 rows x 64 cols:
// 2 m16-stripes x 8 n8-tiles, K chunked BK=16 (2 k8 steps).
// Fragments are PRE-STAGED in smem in mma layout (16B/lane stride,
// conflict-free LDS.128): mainloop = pure frag loads + HMMA.

__device__ __forceinline__ void mma_tf32(float4& d, float a0, float a1, float a2,
                                         float a3, float b0, float b1) {
    asm volatile(
        "mma.sync.aligned.m16n8k8.row.col.f32.tf32.tf32.f32 "
        "{%0,%1,%2,%3}, {%4,%5,%6,%7}, {%8,%9}, {%0,%1,%2,%3};\n"
        : "+f"(d.x), "+f"(d.y), "+f"(d.z), "+f"(d.w)
        : "r"(__float_as_uint(a0)), "r"(__float_as_uint(a1)),
          "r"(__float_as_uint(a2)), "r"(__float_as_uint(a3)),
          "r"(__float_as_uint(b0)), "r"(__float_as_uint(b1)));
}

__device__ __forceinline__ float tf32_hi(float a) {
    return __uint_as_float(__float_as_uint(a) & 0xffffe000u);
}

template <bool RELU_BIAS>
__global__ void __launch_bounds__(256, 2) k_gemm(
    const float* __restrict__ A, const float* __restrict__ W,
    const float* __restrict__ bias, float* __restrict__ Out)
{
    // A frags: [ks(2)][stripe(8)][lane(32)][4]  hi and lo separate (8KB each)
    // B frags: [ks(2)][ntile(16)][lane(32)][4] = {b0hi,b1hi,b0lo,b1lo} (16KB)
    __shared__ float sAh[2 * 8 * 32 * 4];
    __shared__ float sAl[2 * 8 * 32 * 4];
    __shared__ float sB [2 * 16 * 32 * 4];

    const int block_row = blockIdx.x * 128;
    const int tid  = threadIdx.x;
    const int lane = tid & 31;
    const int w    = tid >> 5;      // 0..7
    const int rw   = w >> 1;        // row group: rows rw*32 .. rw*32+31
    const int cw   = w & 1;         // col half:  cols cw*64 .. cw*64+63

    float4 acc0[8], acc1[8];        // [ntile] for stripe0/stripe1
#pragma unroll
    for (int i = 0; i < 8; i++) {
        acc0[i] = make_float4(0.f, 0.f, 0.f, 0.f);
        acc1[i] = make_float4(0.f, 0.f, 0.f, 0.f);
    }

    for (int k0 = 0; k0 < FD; k0 += 16) {
        // ---- stage A chunk (128 rows x 16 k) into mma fragment layout ----
        // 512 float4 loads; element (r, c=q*4+j):
        //   ks=q>>1, chalf=q&1, stripe=r>>4, ghalf=(r&15)>>3, g=r&7, t=j
        //   frag slot = (chalf<<1)|ghalf, lane = g*4+t
        for (int idx = tid; idx < 512; idx += 256) {
            int r = idx >> 2, q = idx & 3;
            int row = block_row + r;
            float4 v = make_float4(0.f, 0.f, 0.f, 0.f);
            if (row < NN)
                v = *reinterpret_cast<const float4*>(&A[row * FD + k0 + q * 4]);
            if (RELU_BIAS) {
                float4 bb = *reinterpret_cast<const float4*>(&bias[k0 + q * 4]);
                v.x = fmaxf(v.x + bb.x, 0.f); v.y = fmaxf(v.y + bb.y, 0.f);
                v.z = fmaxf(v.z + bb.z, 0.f); v.w = fmaxf(v.w + bb.w, 0.f);
            }
            int ks = q >> 1, chalf = q & 1;
            int stripe = r >> 4, r16 = r & 15;
            int ghalf = r16 >> 3, g = r16 & 7;
            int slot = (chalf << 1) | ghalf;
            float vals[4] = { v.x, v.y, v.z, v.w };
#pragma unroll
            for (int j = 0; j < 4; j++) {
                float a  = vals[j];
                float hi = tf32_hi(a);
                int base = ((ks * 8 + stripe) * 32 + (g * 4 + j)) * 4 + slot;
                sAh[base] = hi;
                sAl[base] = a - hi;
            }
        }
        // ---- stage B chunk (16 k x 128 n) into mma fragment layout ----
        // element (kr, n=q*4+j): ks=kr>>3, t=kr&3, khalf=(kr&7)>>2,
        //   ntile=q>>1, g=(q&1)*4+j, lane=g*4+t, slots {khalf, khalf+2}
        for (int idx = tid; idx < 512; idx += 256) {
            int kr = idx >> 5, q = idx & 31;
            float4 v = *reinterpret_cast<const float4*>(&W[(k0 + kr) * FD + q * 4]);
            int ks = kr >> 3, kc = kr & 7;
            int t = kc & 3, khalf = kc >> 2;
            int ntile = q >> 1, gbase = (q & 1) * 4;
            float vals[4] = { v.x, v.y, v.z, v.w };
#pragma unroll
            for (int j = 0; j < 4; j++) {
                float b  = vals[j];
                float hi = tf32_hi(b);
                int base = ((ks * 16 + ntile) * 32 + (gbase + j) * 4 + t) * 4;
                sB[base + khalf]     = hi;
                sB[base + khalf + 2] = b - hi;
            }
        }
        __syncthreads();

#pragma unroll
        for (int ks = 0; ks < 2; ks++) {
            float4 ah0 = *reinterpret_cast<const float4*>(
                &sAh[((ks * 8 + rw * 2 + 0) * 32 + lane) * 4]);
            float4 al0 = *reinterpret_cast<const float4*>(
                &sAl[((ks * 8 + rw * 2 + 0) * 32 + lane) * 4]);
            float4 ah1 = *reinterpret_cast<const float4*>(
                &sAh[((ks * 8 + rw * 2 + 1) * 32 + lane) * 4]);
            float4 al1 = *reinterpret_cast<const float4*>(
                &sAl[((ks * 8 + rw * 2 + 1) * 32 + lane) * 4]);
#pragma unroll
            for (int nt8 = 0; nt8 < 8; nt8++) {
                int nt = cw * 8 + nt8;
                float4 b = *reinterpret_cast<const float4*>(
                    &sB[((ks * 16 + nt) * 32 + lane) * 4]);
                // stripe 0: hi*hi, hi*lo, lo*hi
                mma_tf32(acc0[nt8], ah0.x, ah0.y, ah0.z, ah0.w, b.x, b.y);
                mma_tf32(acc0[nt8], ah0.x, ah0.y, ah0.z, ah0.w, b.z, b.w);
                mma_tf32(acc0[nt8], al0.x, al0.y, al0.z, al0.w, b.x, b.y);
                // stripe 1
                mma_tf32(acc1[nt8], ah1.x, ah1.y, ah1.z, ah1.w, b.x, b.y);
                mma_tf32(acc1[nt8], ah1.x, ah1.y, ah1.z, ah1.w, b.z, b.w);
                mma_tf32(acc1[nt8], al1.x, al1.y, al1.z, al1.w, b.x, b.y);
            }
        }
        __syncthreads();
    }

    // epilogue: d0,d1 -> (row=g, col=2t,2t+1); d2,d3 -> (row=g+8)
    const int g = lane >> 2, t = lane & 3;
#pragma unroll
    for (int s = 0; s < 2; s++) {
        const float4* accs = s ? acc1 : acc0;
        int r0 = block_row + rw * 32 + s * 16 + g;
#pragma unroll
        for (int nt8 = 0; nt8 < 8; nt8++) {
            int col = cw * 64 + nt8 * 8 + t * 2;
            if (r0 < NN)
                *reinterpret_cast<float2*>(&Out[r0 * FD + col]) =
                    make_float2(accs[nt8].x, accs[nt8].y);
            if (r0 + 8 < NN)
                *reinterpret_cast<float2*>(&Out[(r0 + 8) * FD + col]) =
                    make_float2(accs[nt8].z, accs[nt8].w);
        }
    }
}

// ---------------------------------------------------------------------------
// CSR gather aggregation: warp per dst node, lane = one float4 of features.
__global__ void k_gather() {
    int gid = blockIdx.x * blockDim.x + threadIdx.x;
    int n = gid >> 5;
    int lane = gid & 31;
    if (n >= NN) return;

    const float4* hw4 = reinterpret_cast<const float4*>(g_hw);
    int start = g_rowstart[n];
    int cnt   = g_deg[n];

    float4 acc = make_float4(0.f, 0.f, 0.f, 0.f);
    int j = 0;
    for (; j + 4 <= cnt; j += 4) {
        int s0 = g_csrc[start + j + 0];
        int s1 = g_csrc[start + j + 1];
        int s2 = g_csrc[start + j + 2];
        int s3 = g_csrc[start + j + 3];
        float w0 = g_dis[s0], w1 = g_dis[s1], w2 = g_dis[s2], w3 = g_dis[s3];
        float4 v0 = hw4[s0 * 32 + lane];
        float4 v1 = hw4[s1 * 32 + lane];
        float4 v2 = hw4[s2 * 32 + lane];
        float4 v3 = hw4[s3 * 32 + lane];
        acc.x += w0 * v0.x + w1 * v1.x + w2 * v2.x + w3 * v3.x;
        acc.y += w0 * v0.y + w1 * v1.y + w2 * v2.y + w3 * v3.y;
        acc.z += w0 * v0.z + w1 * v1.z + w2 * v2.z + w3 * v3.z;
        acc.w += w0 * v0.w + w1 * v1.w + w2 * v2.w + w3 * v3.w;
    }
    for (; j < cnt; j++) {
        int s = g_csrc[start + j];
        float w = g_dis[s];
        float4 v = hw4[s * 32 + lane];
        acc.x += w * v.x; acc.y += w * v.y;
        acc.z += w * v.z; acc.w += w * v.w;
    }
    float dd = g_dis[n];
    float w2s = dd * dd;
    float4 self = hw4[n * 32 + lane];
    float4 o = make_float4(dd * acc.x + w2s * self.x,
                           dd * acc.y + w2s * self.y,
                           dd * acc.z + w2s * self.z,
                           dd * acc.w + w2s * self.w);
    reinterpret_cast<float4*>(g_agg)[n * 32 + lane] = o;
}

// ---------------------------------------------------------------------------
// pooling over contiguous graph segments + readout, fused. Block per graph.
__global__ void __launch_bounds__(128) k_pool_final(
    const float* __restrict__ b2, const float* __restrict__ Wlin,
    const float* __restrict__ blin, float* __restrict__ out)
{
    __shared__ float sh[128];
    int g = blockIdx.x;
    int f = threadIdx.x;
    int n0 = g_gstart[g], n1 = g_gstart[g + 1];
    int cnt = n1 - n0;

    float acc = 0.0f;
#pragma unroll 4
    for (int n = n0; n < n1; n++) acc += g_agg[n * FD + f];

    float inv = (cnt > 0) ? 1.0f / (float)cnt : 0.0f;
    float pooled = acc * inv + ((cnt > 0) ? b2[f] : 0.0f);
    sh[f] = pooled * Wlin[f];
    __syncthreads();
#pragma unroll
    for (int off = 64; off > 0; off >>= 1) {
        if (f < off) sh[f] += sh[f + off];
        __syncthreads();
    }
    if (f == 0) out[g] = sh[0] + blin[0];
}

// ---------------------------------------------------------------------------
extern "C" void kernel_launch(void* const* d_in, const int* in_sizes, int n_in,
                              void* d_out, int out_size)
{
    const float* x     = (const float*)d_in[0];
    const int*   ei    = (const int*)d_in[1];     // int32
    const int*   batch = (const int*)d_in[2];     // int32
    const float* W1    = (const float*)d_in[3];
    const float* b1    = (const float*)d_in[4];
    const float* W2    = (const float*)d_in[5];
    const float* b2    = (const float*)d_in[6];
    const float* Wlin  = (const float*)d_in[7];
    const float* blin  = (const float*)d_in[8];
    float* out = (float*)d_out;

    void *p_hw, *p_agg;
    cudaGetSymbolAddress(&p_hw,  g_hw);
    cudaGetSymbolAddress(&p_agg, g_agg);
    float* hw  = (float*)p_hw;
    float* agg = (float*)p_agg;

    const int T = 256;
    const int nn_blocks   = (NN + T - 1) / T;
    const int ne_blocks   = (NE + T - 1) / T;
    const int gemm_blocks = (NN + 127) / 128;
    const int gat_blocks  = (NN * 32 + T - 1) / T;

    // Launch order keeps gemm1 at my launch index 3 (0-based) so the ncu
    // capture window (-s 5 -c 1, with 2 harness pre-launches) lands on it.
    k_zero       <<<nn_blocks, T>>>();
    k_count      <<<ne_blocks, T>>>(ei);
    k_scan1      <<<NB_SCAN, SCAN_B>>>();
    k_gemm<false><<<gemm_blocks, T>>>(x, W1, nullptr, hw);   // layer-1 GEMM (no CSR dep)
    k_scan2      <<<1, 128>>>();
    k_scan3      <<<nn_blocks, T>>>();
    k_fill       <<<ne_blocks, T>>>(ei);
    k_gstart     <<<(NN + 1 + T - 1) / T, T>>>(batch);

    // Layer 1 aggregation, then layer 2
    k_gather     <<<gat_blocks, T>>>();
    k_gemm<true> <<<gemm_blocks, T>>>(agg, W2, b1, hw);
    k_gather     <<<gat_blocks, T>>>();

    // Mean-pool (contiguous segments) + readout, b2 folded with empty-graph guard
    k_pool_final <<<NG, 128>>>(b2, Wlin, blin, out);
}

// round 13
// speedup vs baseline: 1.9245x; 1.9245x over previous
#include <cuda_runtime.h>

#define NN 100000
#define NE 600000
#define NG 512
#define FD 128
#define SCAN_B 1024
#define NB_SCAN ((NN + SCAN_B - 1) / SCAN_B)   // 98

// Scratch (allocation-free rule: __device__ globals). No float atomics anywhere.
__device__ float g_hw [NN * FD];   // h @ W
__device__ float g_agg[NN * FD];   // aggregated layer output
__device__ float g_dis[NN];        // deg^{-1/2}
__device__ int   g_deg[NN];        // in-degree (excluding self loop)
__device__ int   g_scan[NN];       // inclusive per-block scan
__device__ int   g_bsum[NB_SCAN];
__device__ int   g_boff[NB_SCAN];
__device__ int   g_rowstart[NN];   // CSR row starts (exclusive scan)
__device__ int   g_cursor[NN];     // fill cursors
__device__ int   g_csrc[NE];       // CSR: src lists grouped by dst
__device__ int   g_gstart[NG + 1]; // graph segment starts (batch is sorted)
__device__ float4 g_bfrag1[16 * 16 * 32];  // W1 mma fragments {b0h,b1h,b0l,b1l}
__device__ float4 g_bfrag2[16 * 16 * 32];  // W2 mma fragments

// ---------------------------------------------------------------------------
__global__ void k_zero() {
    int i = blockIdx.x * blockDim.x + threadIdx.x;
    if (i < NN) g_deg[i] = 0;
}

__global__ void k_count(const int* __restrict__ ei) {
    int e = blockIdx.x * blockDim.x + threadIdx.x;
    if (e < NE) atomicAdd(&g_deg[ei[NE + e]], 1);
}

__global__ void __launch_bounds__(SCAN_B) k_scan1() {
    __shared__ int s[SCAN_B];
    int tid = threadIdx.x;
    int i = blockIdx.x * SCAN_B + tid;
    s[tid] = (i < NN) ? g_deg[i] : 0;
    __syncthreads();
#pragma unroll
    for (int off = 1; off < SCAN_B; off <<= 1) {
        int v = (tid >= off) ? s[tid - off] : 0;
        __syncthreads();
        s[tid] += v;
        __syncthreads();
    }
    if (i < NN) g_scan[i] = s[tid];
    if (tid == SCAN_B - 1) g_bsum[blockIdx.x] = s[tid];
}

__global__ void __launch_bounds__(128) k_scan2() {
    __shared__ int s[128];
    int t = threadIdx.x;
    int v = (t < NB_SCAN) ? g_bsum[t] : 0;
    s[t] = v;
    __syncthreads();
#pragma unroll
    for (int off = 1; off < 128; off <<= 1) {
        int u = (t >= off) ? s[t - off] : 0;
        __syncthreads();
        s[t] += u;
        __syncthreads();
    }
    if (t < NB_SCAN) g_boff[t] = s[t] - v;   // exclusive
}

__global__ void k_scan3() {
    int i = blockIdx.x * blockDim.x + threadIdx.x;
    if (i < NN) {
        int excl = g_scan[i] + g_boff[i >> 10] - g_deg[i];
        g_rowstart[i] = excl;
        g_cursor[i]   = excl;
        g_dis[i] = rsqrtf(1.0f + (float)g_deg[i]);
    }
}

__global__ void k_fill(const int* __restrict__ ei) {
    int e = blockIdx.x * blockDim.x + threadIdx.x;
    if (e < NE) {
        int s = ei[e];
        int d = ei[NE + e];
        int pos = atomicAdd(&g_cursor[d], 1);
        g_csrc[pos] = s;
    }
}

__global__ void k_gstart(const int* __restrict__ batch) {
    int i = blockIdx.x * blockDim.x + threadIdx.x;
    if (i <= NN) {
        int prev = (i == 0) ? -1 : batch[i - 1];
        int cur  = (i < NN) ? batch[i] : NG;
        for (int g = prev + 1; g <= cur; g++) g_gstart[g] = i;
    }
}

// ---------------------------------------------------------------------------
__device__ __forceinline__ float tf32_hi(float a) {
    return __uint_as_float(__float_as_uint(a) & 0xffffe000u);
}

// Precompute W mma fragments (one-time, shared by all GEMM blocks).
// Layout: [ks(16)][nt(16)][lane(32)] float4 = {b0hi, b1hi, b0lo, b1lo}
// lane(g,t): b0 = W[ks*8+t][nt*8+g], b1 = W[ks*8+t+4][nt*8+g]
__global__ void k_bfrag(const float* __restrict__ W, float4* __restrict__ out) {
    int i = blockIdx.x * blockDim.x + threadIdx.x;
    if (i >= 16 * 16 * 32) return;
    int lane = i & 31, nt = (i >> 5) & 15, ks = i >> 9;
    int g = lane >> 2, t = lane & 3;
    int n = nt * 8 + g;
    float b0 = W[(ks * 8 + t) * FD + n];
    float b1 = W[(ks * 8 + t + 4) * FD + n];
    float b0h = tf32_hi(b0), b1h = tf32_hi(b1);
    out[i] = make_float4(b0h, b1h, b0 - b0h, b1 - b1h);
}

__device__ __forceinline__ void mma_tf32(float4& d, float a0, float a1, float a2,
                                         float a3, float b0, float b1) {
    asm volatile(
        "mma.sync.aligned.m16n8k8.row.col.f32.tf32.tf32.f32 "
        "{%0,%1,%2,%3}, {%4,%5,%6,%7}, {%8,%9}, {%0,%1,%2,%3};\n"
        : "+f"(d.x), "+f"(d.y), "+f"(d.z), "+f"(d.w)
        : "r"(__float_as_uint(a0)), "r"(__float_as_uint(a1)),
          "r"(__float_as_uint(a2)), "r"(__float_as_uint(a3)),
          "r"(__float_as_uint(b0)), "r"(__float_as_uint(b1)));
}

// Tensor-core GEMM: Out[NN,128] = f(A)[NN,128] @ W[128,128], split-TF32.
// Block 128x128, 256 threads. Warp = 32 rows x 64 cols (2 m16 stripes, 8 n8).
// A in smem row-major stride 68 (conflict-free frag LDS); hi/lo split in regs.
// B fragments streamed from precomputed global (coalesced LDG.128, L1-hot).
template <bool RELU_BIAS>
__global__ void __launch_bounds__(256, 2) k_gemm(
    const float* __restrict__ A, const float* __restrict__ bias,
    float* __restrict__ Out, const float4* __restrict__ Bfrag)
{
    __shared__ float sA[128 * 68];  // [row][k-chunk 64 + 4 pad]

    const int block_row = blockIdx.x * 128;
    const int tid  = threadIdx.x;
    const int lane = tid & 31;
    const int w    = tid >> 5;
    const int rw   = w >> 1;        // warp row group (32 rows)
    const int cw   = w & 1;         // warp col half (64 cols)
    const int g    = lane >> 2, t = lane & 3;

    float4 acc0[8], acc1[8];
#pragma unroll
    for (int i = 0; i < 8; i++) {
        acc0[i] = make_float4(0.f, 0.f, 0.f, 0.f);
        acc1[i] = make_float4(0.f, 0.f, 0.f, 0.f);
    }

    for (int chunk = 0; chunk < 2; chunk++) {
        const int k0c = chunk * 64;
        // stage A (128 rows x 64 k) row-major: coalesced LDG.128 -> STS.128
        for (int idx = tid; idx < 2048; idx += 256) {
            int r = idx >> 4, q = idx & 15;
            int row = block_row + r;
            float4 v = make_float4(0.f, 0.f, 0.f, 0.f);
            if (row < NN)
                v = *reinterpret_cast<const float4*>(&A[row * FD + k0c + q * 4]);
            if (RELU_BIAS) {
                float4 bb = *reinterpret_cast<const float4*>(&bias[k0c + q * 4]);
                v.x = fmaxf(v.x + bb.x, 0.f); v.y = fmaxf(v.y + bb.y, 0.f);
                v.z = fmaxf(v.z + bb.z, 0.f); v.w = fmaxf(v.w + bb.w, 0.f);
            }
            *reinterpret_cast<float4*>(&sA[r * 68 + q * 4]) = v;
        }
        __syncthreads();

#pragma unroll
        for (int ksl = 0; ksl < 8; ksl++) {
            const int ks = chunk * 8 + ksl;
            const int c  = ksl * 8 + t;
            const int r0 = rw * 32 + g;
            // A fragments, both stripes (conflict-free: stride 68 mod 32 = 4)
            float a00 = sA[(r0     ) * 68 + c];
            float a01 = sA[(r0 +  8) * 68 + c];
            float a02 = sA[(r0     ) * 68 + c + 4];
            float a03 = sA[(r0 +  8) * 68 + c + 4];
            float a10 = sA[(r0 + 16) * 68 + c];
            float a11 = sA[(r0 + 24) * 68 + c];
            float a12 = sA[(r0 + 16) * 68 + c + 4];
            float a13 = sA[(r0 + 24) * 68 + c + 4];
            // register hi/lo split
            float h00 = tf32_hi(a00), h01 = tf32_hi(a01),
                  h02 = tf32_hi(a02), h03 = tf32_hi(a03);
            float h10 = tf32_hi(a10), h11 = tf32_hi(a11),
                  h12 = tf32_hi(a12), h13 = tf32_hi(a13);
            float l00 = a00 - h00, l01 = a01 - h01, l02 = a02 - h02, l03 = a03 - h03;
            float l10 = a10 - h10, l11 = a11 - h11, l12 = a12 - h12, l13 = a13 - h13;

            const float4* bp = &Bfrag[(ks * 16 + cw * 8) * 32 + lane];
#pragma unroll
            for (int nt8 = 0; nt8 < 8; nt8++) {
                float4 b = bp[nt8 * 32];
                // stripe 0: hi*hi, hi*lo, lo*hi
                mma_tf32(acc0[nt8], h00, h01, h02, h03, b.x, b.y);
                mma_tf32(acc0[nt8], h00, h01, h02, h03, b.z, b.w);
                mma_tf32(acc0[nt8], l00, l01, l02, l03, b.x, b.y);
                // stripe 1
                mma_tf32(acc1[nt8], h10, h11, h12, h13, b.x, b.y);
                mma_tf32(acc1[nt8], h10, h11, h12, h13, b.z, b.w);
                mma_tf32(acc1[nt8], l10, l11, l12, l13, b.x, b.y);
            }
        }
        __syncthreads();
    }

    // epilogue: d0,d1 -> (row g, cols 2t,2t+1); d2,d3 -> row g+8
#pragma unroll
    for (int s = 0; s < 2; s++) {
        const float4* accs = s ? acc1 : acc0;
        int r0 = block_row + rw * 32 + s * 16 + g;
#pragma unroll
        for (int nt8 = 0; nt8 < 8; nt8++) {
            int col = cw * 64 + nt8 * 8 + t * 2;
            if (r0 < NN)
                *reinterpret_cast<float2*>(&Out[r0 * FD + col]) =
                    make_float2(accs[nt8].x, accs[nt8].y);
            if (r0 + 8 < NN)
                *reinterpret_cast<float2*>(&Out[(r0 + 8) * FD + col]) =
                    make_float2(accs[nt8].z, accs[nt8].w);
        }
    }
}

// ---------------------------------------------------------------------------
// CSR gather aggregation: warp per dst node, lane = one float4 of features.
__global__ void k_gather() {
    int gid = blockIdx.x * blockDim.x + threadIdx.x;
    int n = gid >> 5;
    int lane = gid & 31;
    if (n >= NN) return;

    const float4* hw4 = reinterpret_cast<const float4*>(g_hw);
    int start = g_rowstart[n];
    int cnt   = g_deg[n];

    float4 acc = make_float4(0.f, 0.f, 0.f, 0.f);
    int j = 0;
    for (; j + 4 <= cnt; j += 4) {
        int s0 = g_csrc[start + j + 0];
        int s1 = g_csrc[start + j + 1];
        int s2 = g_csrc[start + j + 2];
        int s3 = g_csrc[start + j + 3];
        float w0 = g_dis[s0], w1 = g_dis[s1], w2 = g_dis[s2], w3 = g_dis[s3];
        float4 v0 = hw4[s0 * 32 + lane];
        float4 v1 = hw4[s1 * 32 + lane];
        float4 v2 = hw4[s2 * 32 + lane];
        float4 v3 = hw4[s3 * 32 + lane];
        acc.x += w0 * v0.x + w1 * v1.x + w2 * v2.x + w3 * v3.x;
        acc.y += w0 * v0.y + w1 * v1.y + w2 * v2.y + w3 * v3.y;
        acc.z += w0 * v0.z + w1 * v1.z + w2 * v2.z + w3 * v3.z;
        acc.w += w0 * v0.w + w1 * v1.w + w2 * v2.w + w3 * v3.w;
    }
    for (; j < cnt; j++) {
        int s = g_csrc[start + j];
        float w = g_dis[s];
        float4 v = hw4[s * 32 + lane];
        acc.x += w * v.x; acc.y += w * v.y;
        acc.z += w * v.z; acc.w += w * v.w;
    }
    float dd = g_dis[n];
    float w2s = dd * dd;
    float4 self = hw4[n * 32 + lane];
    float4 o = make_float4(dd * acc.x + w2s * self.x,
                           dd * acc.y + w2s * self.y,
                           dd * acc.z + w2s * self.z,
                           dd * acc.w + w2s * self.w);
    reinterpret_cast<float4*>(g_agg)[n * 32 + lane] = o;
}

// ---------------------------------------------------------------------------
// pooling over contiguous graph segments + readout, fused. Block per graph.
__global__ void __launch_bounds__(128) k_pool_final(
    const float* __restrict__ b2, const float* __restrict__ Wlin,
    const float* __restrict__ blin, float* __restrict__ out)
{
    __shared__ float sh[128];
    int g = blockIdx.x;
    int f = threadIdx.x;
    int n0 = g_gstart[g], n1 = g_gstart[g + 1];
    int cnt = n1 - n0;

    float acc = 0.0f;
#pragma unroll 4
    for (int n = n0; n < n1; n++) acc += g_agg[n * FD + f];

    float inv = (cnt > 0) ? 1.0f / (float)cnt : 0.0f;
    float pooled = acc * inv + ((cnt > 0) ? b2[f] : 0.0f);
    sh[f] = pooled * Wlin[f];
    __syncthreads();
#pragma unroll
    for (int off = 64; off > 0; off >>= 1) {
        if (f < off) sh[f] += sh[f + off];
        __syncthreads();
    }
    if (f == 0) out[g] = sh[0] + blin[0];
}

// ---------------------------------------------------------------------------
extern "C" void kernel_launch(void* const* d_in, const int* in_sizes, int n_in,
                              void* d_out, int out_size)
{
    const float* x     = (const float*)d_in[0];
    const int*   ei    = (const int*)d_in[1];     // int32
    const int*   batch = (const int*)d_in[2];     // int32
    const float* W1    = (const float*)d_in[3];
    const float* b1    = (const float*)d_in[4];
    const float* W2    = (const float*)d_in[5];
    const float* b2    = (const float*)d_in[6];
    const float* Wlin  = (const float*)d_in[7];
    const float* blin  = (const float*)d_in[8];
    float* out = (float*)d_out;

    void *p_hw, *p_agg, *p_bf1, *p_bf2;
    cudaGetSymbolAddress(&p_hw,  g_hw);
    cudaGetSymbolAddress(&p_agg, g_agg);
    cudaGetSymbolAddress(&p_bf1, g_bfrag1);
    cudaGetSymbolAddress(&p_bf2, g_bfrag2);
    float*  hw  = (float*)p_hw;
    float*  agg = (float*)p_agg;
    float4* bf1 = (float4*)p_bf1;
    float4* bf2 = (float4*)p_bf2;

    const int T = 256;
    const int nn_blocks   = (NN + T - 1) / T;
    const int ne_blocks   = (NE + T - 1) / T;
    const int gemm_blocks = (NN + 127) / 128;
    const int gat_blocks  = (NN * 32 + T - 1) / T;

    // Launch order keeps gemm<false> at my launch index 3 (0-based) so the
    // ncu capture window (-s 5 -c 1, 2 harness pre-launches) lands on it.
    k_zero       <<<nn_blocks, T>>>();
    k_count      <<<ne_blocks, T>>>(ei);
    k_bfrag      <<<32, 256>>>(W1, bf1);
    k_gemm<false><<<gemm_blocks, T>>>(x, nullptr, hw, bf1);  // layer-1 GEMM
    k_bfrag      <<<32, 256>>>(W2, bf2);
    k_scan1      <<<NB_SCAN, SCAN_B>>>();
    k_scan2      <<<1, 128>>>();
    k_scan3      <<<nn_blocks, T>>>();
    k_fill       <<<ne_blocks, T>>>(ei);
    k_gstart     <<<(NN + 1 + T - 1) / T, T>>>(batch);

    // Layer 1 aggregation, then layer 2
    k_gather     <<<gat_blocks, T>>>();
    k_gemm<true> <<<gemm_blocks, T>>>(agg, b1, hw, bf2);
    k_gather     <<<gat_blocks, T>>>();

    // Mean-pool (contiguous segments) + readout, b2 folded with empty-graph guard
    k_pool_final <<<NG, 128>>>(b2, Wlin, blin, out);
}